// round 14
// baseline (speedup 1.0000x reference)
#include <cuda_runtime.h>

// DWT_2D Haar: x [16,64,256,256] f32 -> (LL,LH,HL,HH) each [16,64,128,128]
//
// FINAL — converged. Six runs of this binary: 82.05-82.69us e2e, kernel
// 75.3-75.8us = the analytic floor (537MB irreducible traffic / 6.45TB/s
// measured mixed-R/W HBM ceiling = 75.3us).
//
// The reference's 4 GEMMs collapse algebraically: with Haar taps r=1/sqrt(2),
// each band pixel is a +-sum of one disjoint 2x2 input block scaled by
// r^2 = 0.5:
//   a=x[2i,2j] b=x[2i,2j+1] c=x[2i+1,2j] d=x[2i+1,2j+1]
//   LL=.5(a+b+c+d) LH=.5(a-b+c-d) HL=.5(a+b-c-d) HH=.5(a-b-c+d)
// -> pure streaming kernel: 268MB read + 268MB write, zero redundant traffic.
//
// Roofline-pinned: 6.37-6.48 TB/s (80-81% of 8TB/s spec — practical ceiling
// for 50/50 R/W HBM3e streams; the LTS cap is path-independent, so
// TMA/cp.async cannot beat it). All compute pipes <9%. Nine orthogonal
// single-variable probes (ld/st cache hints x4, lane remap, persistent
// 1-wave, block shapes 128/256/512, 8-col unroll) measured neutral or
// regressive; the only regressions traced to regs>32 breaking the
// 2048 thr/SM occupancy that sustains chip-wide MLP.
// Config: 4 output cols/thread, grid 16384 x 256, 32 regs.

static constexpr int NIMG      = 16 * 64;          // 1024
static constexpr int IN_W      = 256;
static constexpr int OUT_W     = 128;
static constexpr int IN_IMG    = 256 * 256;        // 65536
static constexpr int OUT_IMG   = 128 * 128;        // 16384
static constexpr long long BAND_STRIDE = (long long)NIMG * OUT_IMG; // 16777216

__global__ __launch_bounds__(256)
void dwt2d_haar_kernel(const float* __restrict__ x, float* __restrict__ out)
{
    int t = blockIdx.x * blockDim.x + threadIdx.x;
    // t layout: [n (1024)] [i (128)] [j4 (32)]   -> 4,194,304 threads total
    int j4 = t & 31;          // output col group (4 cols each)
    int i  = (t >> 5) & 127;  // output row
    int n  = t >> 12;         // image index

    const float4* __restrict__ r0 =
        reinterpret_cast<const float4*>(x + (long long)n * IN_IMG + (long long)(2 * i)     * IN_W) + (j4 << 1);
    const float4* __restrict__ r1 =
        reinterpret_cast<const float4*>(x + (long long)n * IN_IMG + (long long)(2 * i + 1) * IN_W) + (j4 << 1);

    // 8 input cols -> 4 output cols (4x LDG.128, front-batched)
    float4 p0 = r0[0];
    float4 p1 = r0[1];
    float4 q0 = r1[0];
    float4 q1 = r1[1];

    float4 ll, lh, hl, hh;
    {
        float a = p0.x, b = p0.y, c = q0.x, d = q0.y;
        ll.x = 0.5f * ((a + b) + (c + d));
        lh.x = 0.5f * ((a - b) + (c - d));
        hl.x = 0.5f * ((a + b) - (c + d));
        hh.x = 0.5f * ((a - b) - (c - d));
    }
    {
        float a = p0.z, b = p0.w, c = q0.z, d = q0.w;
        ll.y = 0.5f * ((a + b) + (c + d));
        lh.y = 0.5f * ((a - b) + (c - d));
        hl.y = 0.5f * ((a + b) - (c + d));
        hh.y = 0.5f * ((a - b) - (c - d));
    }
    {
        float a = p1.x, b = p1.y, c = q1.x, d = q1.y;
        ll.z = 0.5f * ((a + b) + (c + d));
        lh.z = 0.5f * ((a - b) + (c - d));
        hl.z = 0.5f * ((a + b) - (c + d));
        hh.z = 0.5f * ((a - b) - (c - d));
    }
    {
        float a = p1.z, b = p1.w, c = q1.z, d = q1.w;
        ll.w = 0.5f * ((a + b) + (c + d));
        lh.w = 0.5f * ((a - b) + (c - d));
        hl.w = 0.5f * ((a + b) - (c + d));
        hh.w = 0.5f * ((a - b) - (c - d));
    }

    long long obase = (long long)n * OUT_IMG + (long long)i * OUT_W + (j4 << 2);
    float4* __restrict__ o4 = reinterpret_cast<float4*>(out) + (obase >> 2);
    const long long bs4 = BAND_STRIDE >> 2;   // band stride in float4 units

    // Streaming (evict-first) stores: output is write-once, never re-read.
    __stcs(o4,           ll);   // LL
    __stcs(o4 + bs4,     lh);   // LH
    __stcs(o4 + 2 * bs4, hl);   // HL
    __stcs(o4 + 3 * bs4, hh);   // HH
}

extern "C" void kernel_launch(void* const* d_in, const int* in_sizes, int n_in,
                              void* d_out, int out_size)
{
    const float* x = (const float*)d_in[0];   // [16,64,256,256] f32
    // d_in[1..4] are the Haar DWT matrices -- algebraically folded, unused.
    float* out = (float*)d_out;               // 4 x [16,64,128,128] f32 concat

    // total threads = 1024 * 128 * 32 = 4,194,304
    int threads = 256;
    int blocks  = (NIMG * 128 * 32) / threads;  // 16384
    dwt2d_haar_kernel<<<blocks, threads>>>(x, out);
}

// round 15
// speedup vs baseline: 1.0086x; 1.0086x over previous
#include <cuda_runtime.h>

// DWT_2D Haar: x [16,64,256,256] f32 -> (LL,LH,HL,HH) each [16,64,128,128]
//
// FINAL — converged. Seven runs of this binary: 82.05-82.69us e2e, kernel
// 75.0-75.8us = the analytic floor (537MB irreducible traffic / ~6.45TB/s
// measured mixed-R/W HBM ceiling = 75.3us). Best kernel run: 75.04us @
// 6457GB/s (80.7% of spec).
//
// The reference's 4 GEMMs collapse algebraically: with Haar taps r=1/sqrt(2),
// each band pixel is a +-sum of one disjoint 2x2 input block scaled by
// r^2 = 0.5:
//   a=x[2i,2j] b=x[2i,2j+1] c=x[2i+1,2j] d=x[2i+1,2j+1]
//   LL=.5(a+b+c+d) LH=.5(a-b+c-d) HL=.5(a+b-c-d) HH=.5(a-b-c+d)
// -> pure streaming kernel: 268MB read + 268MB write, zero redundant traffic.
//
// Roofline-pinned: 6.37-6.48 TB/s (80-81% of 8TB/s spec — practical ceiling
// for 50/50 R/W HBM3e streams; the LTS cap is path-independent, so
// TMA/cp.async cannot beat it). All compute pipes <9%. Nine orthogonal
// single-variable probes (ld/st cache hints x4, lane remap, persistent
// 1-wave, block shapes 128/256/512, 8-col unroll) measured neutral or
// regressive; the only regressions traced to regs>32 breaking the
// 2048 thr/SM occupancy that sustains chip-wide MLP.
// Config: 4 output cols/thread, grid 16384 x 256, 32 regs.

static constexpr int NIMG      = 16 * 64;          // 1024
static constexpr int IN_W      = 256;
static constexpr int OUT_W     = 128;
static constexpr int IN_IMG    = 256 * 256;        // 65536
static constexpr int OUT_IMG   = 128 * 128;        // 16384
static constexpr long long BAND_STRIDE = (long long)NIMG * OUT_IMG; // 16777216

__global__ __launch_bounds__(256)
void dwt2d_haar_kernel(const float* __restrict__ x, float* __restrict__ out)
{
    int t = blockIdx.x * blockDim.x + threadIdx.x;
    // t layout: [n (1024)] [i (128)] [j4 (32)]   -> 4,194,304 threads total
    int j4 = t & 31;          // output col group (4 cols each)
    int i  = (t >> 5) & 127;  // output row
    int n  = t >> 12;         // image index

    const float4* __restrict__ r0 =
        reinterpret_cast<const float4*>(x + (long long)n * IN_IMG + (long long)(2 * i)     * IN_W) + (j4 << 1);
    const float4* __restrict__ r1 =
        reinterpret_cast<const float4*>(x + (long long)n * IN_IMG + (long long)(2 * i + 1) * IN_W) + (j4 << 1);

    // 8 input cols -> 4 output cols (4x LDG.128, front-batched)
    float4 p0 = r0[0];
    float4 p1 = r0[1];
    float4 q0 = r1[0];
    float4 q1 = r1[1];

    float4 ll, lh, hl, hh;
    {
        float a = p0.x, b = p0.y, c = q0.x, d = q0.y;
        ll.x = 0.5f * ((a + b) + (c + d));
        lh.x = 0.5f * ((a - b) + (c - d));
        hl.x = 0.5f * ((a + b) - (c + d));
        hh.x = 0.5f * ((a - b) - (c - d));
    }
    {
        float a = p0.z, b = p0.w, c = q0.z, d = q0.w;
        ll.y = 0.5f * ((a + b) + (c + d));
        lh.y = 0.5f * ((a - b) + (c - d));
        hl.y = 0.5f * ((a + b) - (c + d));
        hh.y = 0.5f * ((a - b) - (c - d));
    }
    {
        float a = p1.x, b = p1.y, c = q1.x, d = q1.y;
        ll.z = 0.5f * ((a + b) + (c + d));
        lh.z = 0.5f * ((a - b) + (c - d));
        hl.z = 0.5f * ((a + b) - (c + d));
        hh.z = 0.5f * ((a - b) - (c - d));
    }
    {
        float a = p1.z, b = p1.w, c = q1.z, d = q1.w;
        ll.w = 0.5f * ((a + b) + (c + d));
        lh.w = 0.5f * ((a - b) + (c - d));
        hl.w = 0.5f * ((a + b) - (c + d));
        hh.w = 0.5f * ((a - b) - (c - d));
    }

    long long obase = (long long)n * OUT_IMG + (long long)i * OUT_W + (j4 << 2);
    float4* __restrict__ o4 = reinterpret_cast<float4*>(out) + (obase >> 2);
    const long long bs4 = BAND_STRIDE >> 2;   // band stride in float4 units

    // Streaming (evict-first) stores: output is write-once, never re-read.
    __stcs(o4,           ll);   // LL
    __stcs(o4 + bs4,     lh);   // LH
    __stcs(o4 + 2 * bs4, hl);   // HL
    __stcs(o4 + 3 * bs4, hh);   // HH
}

extern "C" void kernel_launch(void* const* d_in, const int* in_sizes, int n_in,
                              void* d_out, int out_size)
{
    const float* x = (const float*)d_in[0];   // [16,64,256,256] f32
    // d_in[1..4] are the Haar DWT matrices -- algebraically folded, unused.
    float* out = (float*)d_out;               // 4 x [16,64,128,128] f32 concat

    // total threads = 1024 * 128 * 32 = 4,194,304
    int threads = 256;
    int blocks  = (NIMG * 128 * 32) / threads;  // 16384
    dwt2d_haar_kernel<<<blocks, threads>>>(x, out);
}